// round 6
// baseline (speedup 1.0000x reference)
#include <cuda_runtime.h>

// LSTM: B=512, T=1000, IN=39, H=64 (4H=256 gates), OUT=48.
// R6: two kernels.
//  1) xproj: xg[b,t,g] = W_ih·x + b_ih + b_hh  (one big GEMM, 512MB scratch)
//  2) recurrence: persistent 128 CTAs x 512 threads.
//     Breaks the R1-R5 broadcast invariant (832 wf/SM/step): h stored
//     TRANSPOSED as (r0,r1,r2,r3) per unit; weights pre-DUPLICATED (w,w)
//     in regs; one broadcast LDS.128 feeds 2 gates x 2 rowpairs = 4 FFMA2.
//     Phase A: 256 wf/SM/step. Output head: W_out dup'd in regs of threads
//     128-511, split-k partials in SMEM, reduce+store pipelined 1 step late.

#define B_    512
#define T_    1000
#define IN_   39
#define H_    64
#define G_    256   // 4*H
#define OUT_  48
#define ROWS  4
#define CTAS  (B_/ROWS)   // 128
#define NTHR  512

typedef unsigned long long u64;

__device__ float g_xg[(size_t)B_ * T_ * G_];   // 512 MB scratch: x-projection

__device__ __forceinline__ u64 fma2(u64 a, u64 b, u64 c) {
    u64 d;
    asm("fma.rn.f32x2 %0, %1, %2, %3;" : "=l"(d) : "l"(a), "l"(b), "l"(c));
    return d;
}
__device__ __forceinline__ u64 add2(u64 a, u64 b) {
    u64 d;
    asm("add.rn.f32x2 %0, %1, %2;" : "=l"(d) : "l"(a), "l"(b));
    return d;
}
__device__ __forceinline__ u64 pack2(float lo, float hi) {
    u64 d;
    asm("mov.b64 %0, {%1, %2};" : "=l"(d) : "f"(lo), "f"(hi));
    return d;
}
__device__ __forceinline__ void unpack2(u64 v, float &lo, float &hi) {
    asm("mov.b64 {%0, %1}, %2;" : "=f"(lo), "=f"(hi) : "l"(v));
}
__device__ __forceinline__ float sigm(float x) {
    return __fdividef(1.0f, 1.0f + __expf(-x));
}
__device__ __forceinline__ float tanh_(float x) {
    float e = __expf(2.0f * x);               // 0 .. inf
    return 1.0f - __fdividef(2.0f, e + 1.0f); // -1 .. 1, no inf/inf
}

// ============================ kernel 1: x projection ========================
// xg[bt][g] = sum_i x[bt][i]*W_ih[g][i] + b_ih[g] + b_hh[g]
#define PT_BT 32
__global__ void __launch_bounds__(256)
xproj_kernel(const float* __restrict__ x,
             const float* __restrict__ W_ih,
             const float* __restrict__ b_ih,
             const float* __restrict__ b_hh)
{
    __shared__ __align__(16) float xsp[PT_BT][40];
    const int g = threadIdx.x;                       // 0..255
    const size_t bt0 = (size_t)blockIdx.x * PT_BT;

    u64 w2[20];
    #pragma unroll
    for (int k2 = 0; k2 < 19; k2++)
        w2[k2] = pack2(W_ih[g*IN_ + 2*k2], W_ih[g*IN_ + 2*k2 + 1]);
    w2[19] = pack2(W_ih[g*IN_ + 38], 0.0f);
    const float bias = b_ih[g] + b_hh[g];

    for (int idx = threadIdx.x; idx < PT_BT*40; idx += 256) {
        int r = idx / 40, i = idx % 40;
        xsp[r][i] = (i < IN_) ? x[(bt0 + r)*IN_ + i] : 0.0f;
    }
    __syncthreads();

    float* outp = g_xg + bt0 * G_ + g;
    #pragma unroll 4
    for (int r = 0; r < PT_BT; r++) {
        const ulonglong2* xp = (const ulonglong2*)xsp[r];
        u64 acc = pack2(bias, 0.0f);
        #pragma unroll
        for (int k = 0; k < 10; k++) {
            ulonglong2 q = xp[k];
            acc = fma2(w2[2*k    ], q.x, acc);
            acc = fma2(w2[2*k + 1], q.y, acc);
        }
        float lo, hi; unpack2(acc, lo, hi);
        outp[(size_t)r * G_] = lo + hi;
    }
}

// ============================ kernel 2: recurrence ==========================
__global__ void __launch_bounds__(NTHR, 1)
lstm_rec_kernel(const float* __restrict__ W_hh,
                const float* __restrict__ W_out,
                const float* __restrict__ b_out,
                float* __restrict__ out)
{
    __shared__ __align__(16) ulonglong2 hsT[H_];     // per unit: (h_r0,h_r1 | h_r2,h_r3)
    __shared__ __align__(16) float g4[4][ROWS][G_];  // gate partials per k-split, 16KB
    __shared__ __align__(16) u64 pc3[2][8][50];      // out-head partials (padded)

    const int tid  = threadIdx.x;
    const int row0 = blockIdx.x * ROWS;

    // ---- Phase A identity: thread = (gate-pair gp, k-split ks) ----
    const int gp = tid & 127;          // gates gp and gp+128
    const int ks = tid >> 7;           // 0..3, k in [16ks, 16ks+16)
    u64 w0[16], w1[16];                // duplicated (w,w) weight pairs
    #pragma unroll
    for (int j = 0; j < 16; j++) {
        int k = ks*16 + j;
        float a = W_hh[gp*H_ + k];
        float b = W_hh[(gp + 128)*H_ + k];
        w0[j] = pack2(a, a);
        w1[j] = pack2(b, b);
    }
    const u64 zero2 = pack2(0.0f, 0.0f);

    // ---- Phase B identity (tid<128): thread = (unit bu, rowpair bp) ----
    const int bu = tid & 63;
    const int bp = (tid >> 6) & 1;     // rows 2bp, 2bp+1
    float c0 = 0.0f, c1 = 0.0f;        // cell states
    const size_t xgb0 = (size_t)(row0 + 2*bp    ) * T_ * G_;
    const size_t xgb1 = (size_t)(row0 + 2*bp + 1) * T_ * G_;
    float xgr[8];                      // [row(2)][class(4)] prefetched xg
    if (tid < 128) {
        #pragma unroll
        for (int c = 0; c < 4; c++) {
            xgr[c    ] = g_xg[xgb0 + bu + 64*c];
            xgr[4 + c] = g_xg[xgb1 + bu + 64*c];
        }
    }

    // ---- Phase C1 identity (tid>=128): thread = (output co, k-chunk ckc) ----
    const int tpc = tid - 128;
    const int co  = tpc >> 3;          // 0..47
    const int ckc = tpc & 7;           // 0..7, k in [8ckc, 8ckc+8)
    u64 wo[8];
    u64 cbias = zero2;
    if (tid >= 128) {
        #pragma unroll
        for (int j = 0; j < 8; j++) {
            float v = W_out[co*H_ + ckc*8 + j];
            wo[j] = pack2(v, v);
        }
        if (ckc == 0) { float bo = b_out[co]; cbias = pack2(bo, bo); }
    }

    // ---- Phase C2 identity (tid in [128,224)): thread = (output o2, rowpair p2) ----
    const int i2 = tid - 128;          // valid role when i2 < 96
    const int o2 = i2 % 48;
    const int p2 = i2 / 48;

    if (tid < H_) hsT[tid] = make_ulonglong2(0ull, 0ull);
    __syncthreads();

    for (int t = 0; t < T_; t++) {
        // ---- Phase A: h-part gate partials. 16 broadcast LDS.128 feed 64 FFMA2 ----
        {
            u64 a00 = zero2, a01 = zero2, a10 = zero2, a11 = zero2;
            #pragma unroll
            for (int j = 0; j < 16; j++) {
                ulonglong2 q = hsT[ks*16 + j];
                a00 = fma2(w0[j], q.x, a00);   // gate gp,     rows 0,1
                a01 = fma2(w0[j], q.y, a01);   // gate gp,     rows 2,3
                a10 = fma2(w1[j], q.x, a10);   // gate gp+128, rows 0,1
                a11 = fma2(w1[j], q.y, a11);   // gate gp+128, rows 2,3
            }
            float u, v;
            unpack2(a00, u, v); g4[ks][0][gp      ] = u; g4[ks][1][gp      ] = v;
            unpack2(a01, u, v); g4[ks][2][gp      ] = u; g4[ks][3][gp      ] = v;
            unpack2(a10, u, v); g4[ks][0][gp + 128] = u; g4[ks][1][gp + 128] = v;
            unpack2(a11, u, v); g4[ks][2][gp + 128] = u; g4[ks][3][gp + 128] = v;
        }
        __syncthreads();   // bar1

        if (tid < 128) {
            // ---- Phase B: sum partials + xg, activations, state update ----
            float hv0, hv1;
            #pragma unroll
            for (int rr = 0; rr < 2; rr++) {
                const int r = 2*bp + rr;
                float pi_ = xgr[rr*4 + 0] + g4[0][r][bu      ] + g4[1][r][bu      ]
                                          + g4[2][r][bu      ] + g4[3][r][bu      ];
                float pf_ = xgr[rr*4 + 1] + g4[0][r][bu +  64] + g4[1][r][bu +  64]
                                          + g4[2][r][bu +  64] + g4[3][r][bu +  64];
                float pg_ = xgr[rr*4 + 2] + g4[0][r][bu + 128] + g4[1][r][bu + 128]
                                          + g4[2][r][bu + 128] + g4[3][r][bu + 128];
                float po_ = xgr[rr*4 + 3] + g4[0][r][bu + 192] + g4[1][r][bu + 192]
                                          + g4[2][r][bu + 192] + g4[3][r][bu + 192];
                float iv = sigm(pi_), fv = sigm(pf_);
                float gv = tanh_(pg_), ov = sigm(po_);
                float cc = rr ? c1 : c0;
                cc = fv * cc + iv * gv;
                if (rr) c1 = cc; else c0 = cc;
                float h = ov * tanh_(cc);
                if (rr) hv1 = h; else hv0 = h;
            }
            ((u64*)&hsT[bu])[bp] = pack2(hv0, hv1);
            // prefetch next step's xg (full step of latency cover)
            if (t + 1 < T_) {
                const size_t o0 = xgb0 + (size_t)(t + 1) * G_;
                const size_t o1 = xgb1 + (size_t)(t + 1) * G_;
                #pragma unroll
                for (int c = 0; c < 4; c++) {
                    xgr[c    ] = g_xg[o0 + bu + 64*c];
                    xgr[4 + c] = g_xg[o1 + bu + 64*c];
                }
            }
        } else if (i2 < 96 && t > 0) {
            // ---- Phase C2: reduce step t-1 out-head partials, emit y ----
            u64 s = pc3[p2][0][o2];
            #pragma unroll
            for (int kc = 1; kc < 8; kc++) s = add2(s, pc3[p2][kc][o2]);
            float z0, z1; unpack2(s, z0, z1);
            out[((size_t)(row0 + 2*p2    ) * T_ + (t-1)) * OUT_ + o2] = sigm(z0);
            out[((size_t)(row0 + 2*p2 + 1) * T_ + (t-1)) * OUT_ + o2] = sigm(z1);
        }
        __syncthreads();   // bar2

        // ---- Phase C1: out-head partials for step t (uses fresh h) ----
        if (tid >= 128) {
            u64 c01 = cbias, c23 = cbias;
            #pragma unroll
            for (int j = 0; j < 8; j++) {
                ulonglong2 q = hsT[ckc*8 + j];
                c01 = fma2(wo[j], q.x, c01);
                c23 = fma2(wo[j], q.y, c23);
            }
            pc3[0][ckc][co] = c01;
            pc3[1][ckc][co] = c23;
        }
        // no barrier here: next Phase A only READS hsT (also read by C1);
        // pc3 written here is read by C2 only after the next bar1.
    }

    // ---- epilogue: emit final step t = T-1 ----
    __syncthreads();
    if (tid >= 128 && i2 < 96) {
        u64 s = pc3[p2][0][o2];
        #pragma unroll
        for (int kc = 1; kc < 8; kc++) s = add2(s, pc3[p2][kc][o2]);
        float z0, z1; unpack2(s, z0, z1);
        out[((size_t)(row0 + 2*p2    ) * T_ + (T_-1)) * OUT_ + o2] = sigm(z0);
        out[((size_t)(row0 + 2*p2 + 1) * T_ + (T_-1)) * OUT_ + o2] = sigm(z1);
    }
}

extern "C" void kernel_launch(void* const* d_in, const int* in_sizes, int n_in,
                              void* d_out, int out_size)
{
    (void)in_sizes; (void)n_in; (void)out_size;
    const float* x     = (const float*)d_in[0];
    const float* W_ih  = (const float*)d_in[1];
    const float* W_hh  = (const float*)d_in[2];
    const float* b_ih  = (const float*)d_in[3];
    const float* b_hh  = (const float*)d_in[4];
    const float* W_out = (const float*)d_in[5];
    const float* b_out = (const float*)d_in[6];
    float* out = (float*)d_out;

    xproj_kernel<<<(B_*T_)/PT_BT, 256>>>(x, W_ih, b_ih, b_hh);
    lstm_rec_kernel<<<CTAS, NTHR>>>(W_hh, W_out, b_out, out);
}

// round 7
// speedup vs baseline: 1.8282x; 1.8282x over previous
#include <cuda_runtime.h>

// LSTM: B=512, T=1000, IN=39, H=64 (4H=256 gates), OUT=48.
// R7: two kernels, both using the dup-weight + row-packed-operand T-layout
// so one broadcast LDS.128 feeds 8 FFMA2 (xproj: 4 bt-rows x dup-w; rec:
// 4 gate-classes x 2 rowpairs).
//  - xproj_T: xg[bt][g] = W_ih.x + b, 32-bt tile per CTA (~150us vs R6 410us)
//  - lstm_rec: 128 CTAs x 256 thr. Phase A thread=(unit,k-quarter): all 4
//    classes of one unit, 16 LDS.128 -> 128 FFMA2. Phase B thread=(unit,row):
//    16 coalesced scalar LDS + 4 acts (2 warps/SMSP, unlike R6's 1).
//    Head: dup-W_out in regs, partials reduced one step late (no extra bar).

#define B_    512
#define T_    1000
#define IN_   39
#define H_    64
#define G_    256
#define OUT_  48
#define ROWS  4
#define CTAS  (B_/ROWS)   // 128
#define NTHR  256
#define XTILE 32

typedef unsigned long long u64;

__device__ float g_xg[(size_t)B_ * T_ * G_];   // 512 MB x-projection scratch

__device__ __forceinline__ u64 fma2(u64 a, u64 b, u64 c) {
    u64 d;
    asm("fma.rn.f32x2 %0, %1, %2, %3;" : "=l"(d) : "l"(a), "l"(b), "l"(c));
    return d;
}
__device__ __forceinline__ u64 add2(u64 a, u64 b) {
    u64 d;
    asm("add.rn.f32x2 %0, %1, %2;" : "=l"(d) : "l"(a), "l"(b));
    return d;
}
__device__ __forceinline__ u64 pack2(float lo, float hi) {
    u64 d;
    asm("mov.b64 %0, {%1, %2};" : "=l"(d) : "f"(lo), "f"(hi));
    return d;
}
__device__ __forceinline__ void unpack2(u64 v, float &lo, float &hi) {
    asm("mov.b64 {%0, %1}, %2;" : "=f"(lo), "=f"(hi) : "l"(v));
}
__device__ __forceinline__ float sigm(float x) {
    return __fdividef(1.0f, 1.0f + __expf(-x));
}
__device__ __forceinline__ float tanh_(float x) {
    float e = __expf(2.0f * x);
    return 1.0f - __fdividef(2.0f, e + 1.0f);
}

// ====================== kernel 1: x projection (T-layout) ===================
// Thread = gate g. Tile = 32 consecutive bt rows. Operands staged transposed:
// xT[k][bt] so one broadcast LDS.128 (4 bt of one k) feeds 2 FFMA2 with a
// dup'd weight. 312 LDS.128 + 624 FFMA2 per thread per tile.
__global__ void __launch_bounds__(256)
xproj_T(const float* __restrict__ x,
        const float* __restrict__ W_ih,
        const float* __restrict__ b_ih,
        const float* __restrict__ b_hh)
{
    __shared__ __align__(16) float xT[IN_][XTILE];   // [k][bt]
    const int g = threadIdx.x;
    const size_t bt0 = (size_t)blockIdx.x * XTILE;

    u64 w[IN_];
    #pragma unroll
    for (int k = 0; k < IN_; k++) {
        float v = W_ih[g*IN_ + k];
        w[k] = pack2(v, v);
    }
    const float bias = b_ih[g] + b_hh[g];
    const u64 bias2 = pack2(bias, bias);

    // stage transposed: lanes walk bt (coalesced STS), scattered LDG (L2-cached)
    for (int idx = threadIdx.x; idx < IN_*XTILE; idx += 256) {
        int r = idx & (XTILE-1), i = idx >> 5;
        xT[i][r] = x[(bt0 + r)*IN_ + i];
    }
    __syncthreads();

    u64 acc[XTILE/2];
    #pragma unroll
    for (int p = 0; p < XTILE/2; p++) acc[p] = bias2;

    #pragma unroll
    for (int k = 0; k < IN_; k++) {
        const ulonglong2* xp = (const ulonglong2*)xT[k];
        const u64 wk = w[k];
        #pragma unroll
        for (int q = 0; q < XTILE/4; q++) {
            ulonglong2 v = xp[q];          // 4 bt rows of element k
            acc[2*q    ] = fma2(wk, v.x, acc[2*q    ]);
            acc[2*q + 1] = fma2(wk, v.y, acc[2*q + 1]);
        }
    }

    float* outp = g_xg + bt0 * G_ + g;     // lanes g-consecutive -> coalesced
    #pragma unroll
    for (int p = 0; p < XTILE/2; p++) {
        float a, b; unpack2(acc[p], a, b);
        outp[(size_t)(2*p    ) * G_] = a;
        outp[(size_t)(2*p + 1) * G_] = b;
    }
}

// ====================== kernel 2: recurrence ================================
__global__ void __launch_bounds__(NTHR, 1)
lstm_rec(const float* __restrict__ W_hh,
         const float* __restrict__ W_out,
         const float* __restrict__ b_out,
         float* __restrict__ out)
{
    __shared__ __align__(16) float hsT4[H_][4];        // [unit][row], 16B/unit
    __shared__ __align__(16) float pq[4][4][4][H_];    // [ks][class][row][u] 16KB
    __shared__ __align__(16) u64   pc[4][2][OUT_];     // [kc][rowpair][o] 3KB

    const int tid  = threadIdx.x;
    const int row0 = blockIdx.x * ROWS;

    // ---- Phase A identity: (unit ua, k-quarter ks); gates = ua + 64c ----
    const int ua = tid & 63;
    const int ks = tid >> 6;                 // 0..3, k in [16ks,16ks+16)
    u64 wA[4][16];                           // dup (w,w) per class per k
    #pragma unroll
    for (int c = 0; c < 4; c++)
        #pragma unroll
        for (int j = 0; j < 16; j++) {
            float v = W_hh[(c*64 + ua)*H_ + ks*16 + j];
            wA[c][j] = pack2(v, v);
        }
    const u64 zero2 = pack2(0.0f, 0.0f);

    // ---- Phase B identity: (unit ub, row rb); cell state in register ----
    const int ub = tid & 63;
    const int rb = tid >> 6;
    float cst = 0.0f;
    const size_t xgbase = ((size_t)(row0 + rb) * T_) * G_ + ub;
    float xg0 = g_xg[xgbase      ];
    float xg1 = g_xg[xgbase +  64];
    float xg2 = g_xg[xgbase + 128];
    float xg3 = g_xg[xgbase + 192];

    // ---- head C1 identity (tid<192): (output co, k-quarter kc) ----
    const int co = tid % 48;
    const int kc = tid / 48;                 // 0..3 valid when tid<192
    u64 wo[16];
    u64 cb2 = zero2;
    if (tid < 192) {
        #pragma unroll
        for (int j = 0; j < 16; j++) {
            float v = W_out[co*H_ + kc*16 + j];
            wo[j] = pack2(v, v);
        }
        if (kc == 0) { float b = b_out[co]; cb2 = pack2(b, b); }
    }
    // ---- head C2 identity (tid<96): (output co2, rowpair rp2) ----
    const int co2 = tid % 48;
    const int rp2 = tid / 48;                // 0..1 valid when tid<96

    if (tid < H_) {
        hsT4[tid][0] = 0.0f; hsT4[tid][1] = 0.0f;
        hsT4[tid][2] = 0.0f; hsT4[tid][3] = 0.0f;
    }
    __syncthreads();

    for (int t = 0; t < T_; t++) {
        // ---- Phase A: 16 broadcast LDS.128 -> 128 FFMA2 ----
        {
            u64 a01[4] = {zero2, zero2, zero2, zero2};
            u64 a23[4] = {zero2, zero2, zero2, zero2};
            const ulonglong2* hp = (const ulonglong2*)hsT4 + ks*16;
            #pragma unroll
            for (int j = 0; j < 16; j++) {
                ulonglong2 q = hp[j];        // .x=(r0,r1) .y=(r2,r3) of unit
                #pragma unroll
                for (int c = 0; c < 4; c++) {
                    a01[c] = fma2(wA[c][j], q.x, a01[c]);
                    a23[c] = fma2(wA[c][j], q.y, a23[c]);
                }
            }
            #pragma unroll
            for (int c = 0; c < 4; c++) {
                float v0, v1;
                unpack2(a01[c], v0, v1);
                pq[ks][c][0][ua] = v0; pq[ks][c][1][ua] = v1;
                unpack2(a23[c], v0, v1);
                pq[ks][c][2][ua] = v0; pq[ks][c][3][ua] = v1;
            }
        }
        __syncthreads();   // bar1

        // ---- head C2: reduce step t-1 partials, emit y (tid<96) ----
        if (tid < 96 && t > 0) {
            u64 s = add2(add2(pc[0][rp2][co2], pc[1][rp2][co2]),
                         add2(pc[2][rp2][co2], pc[3][rp2][co2]));
            float z0, z1; unpack2(s, z0, z1);
            out[((size_t)(row0 + 2*rp2    ) * T_ + (t-1)) * OUT_ + co2] = sigm(z0);
            out[((size_t)(row0 + 2*rp2 + 1) * T_ + (t-1)) * OUT_ + co2] = sigm(z1);
        }

        // ---- Phase B: sum partials + xg, activations, state update ----
        {
            float si = xg0 + ((pq[0][0][rb][ub] + pq[1][0][rb][ub])
                            + (pq[2][0][rb][ub] + pq[3][0][rb][ub]));
            float sf = xg1 + ((pq[0][1][rb][ub] + pq[1][1][rb][ub])
                            + (pq[2][1][rb][ub] + pq[3][1][rb][ub]));
            float sg = xg2 + ((pq[0][2][rb][ub] + pq[1][2][rb][ub])
                            + (pq[2][2][rb][ub] + pq[3][2][rb][ub]));
            float so = xg3 + ((pq[0][3][rb][ub] + pq[1][3][rb][ub])
                            + (pq[2][3][rb][ub] + pq[3][3][rb][ub]));
            float iv = sigm(si), fv = sigm(sf);
            float gv = tanh_(sg), ov = sigm(so);
            cst = fv * cst + iv * gv;
            hsT4[ub][rb] = ov * tanh_(cst);

            if (t + 1 < T_) {                // prefetch next xg (full-step cover)
                const size_t o = xgbase + (size_t)(t + 1) * G_;
                xg0 = g_xg[o      ]; xg1 = g_xg[o +  64];
                xg2 = g_xg[o + 128]; xg3 = g_xg[o + 192];
            }
        }
        __syncthreads();   // bar2

        // ---- head C1: out-head partials for step t (fresh h) ----
        if (tid < 192) {
            u64 a01 = cb2, a23 = cb2;
            const ulonglong2* hp = (const ulonglong2*)hsT4 + kc*16;
            #pragma unroll
            for (int j = 0; j < 16; j++) {
                ulonglong2 q = hp[j];
                a01 = fma2(wo[j], q.x, a01);
                a23 = fma2(wo[j], q.y, a23);
            }
            pc[kc][0][co] = a01;
            pc[kc][1][co] = a23;
        }
        // no bar: next Phase A only reads hsT (C1 also reads it); pq writes of
        // A(t+1) are safe (B(t) readers finished before bar2); pc written here
        // is read by C2 only after the next bar1.
    }

    // ---- epilogue: emit t = T-1 ----
    __syncthreads();
    if (tid < 96) {
        u64 s = add2(add2(pc[0][rp2][co2], pc[1][rp2][co2]),
                     add2(pc[2][rp2][co2], pc[3][rp2][co2]));
        float z0, z1; unpack2(s, z0, z1);
        out[((size_t)(row0 + 2*rp2    ) * T_ + (T_-1)) * OUT_ + co2] = sigm(z0);
        out[((size_t)(row0 + 2*rp2 + 1) * T_ + (T_-1)) * OUT_ + co2] = sigm(z1);
    }
}

extern "C" void kernel_launch(void* const* d_in, const int* in_sizes, int n_in,
                              void* d_out, int out_size)
{
    (void)in_sizes; (void)n_in; (void)out_size;
    const float* x     = (const float*)d_in[0];
    const float* W_ih  = (const float*)d_in[1];
    const float* W_hh  = (const float*)d_in[2];
    const float* b_ih  = (const float*)d_in[3];
    const float* b_hh  = (const float*)d_in[4];
    const float* W_out = (const float*)d_in[5];
    const float* b_out = (const float*)d_in[6];
    float* out = (float*)d_out;

    xproj_T<<<(B_*T_)/XTILE, 256>>>(x, W_ih, b_ih, b_hh);
    lstm_rec<<<CTAS, NTHR>>>(W_hh, W_out, b_out, out);
}